// round 11
// baseline (speedup 1.0000x reference)
#include <cuda_runtime.h>
#include <cuda_bf16.h>
#include <mma.h>
#include <math.h>

using namespace nvcuda;

#define NN   10000
#define NPAD 10112          // 79 * 128
#define EE   320000
#define DIN  128
#define DHID 128
#define DOUT 64
#define NT   79             // number of 128-tiles
#define NTRI (NT*(NT+1)/2)  // 3160 upper-triangular tiles

// ---------------- scratch (static __device__ globals: allocation-free) ----------------
__device__ __nv_bfloat16 g_xhi[NN*DIN];     // bf16 hi/lo split of x
__device__ __nv_bfloat16 g_xlo[NN*DIN];
__device__ __nv_bfloat16 g_B0hi[DIN*256];   // [Wrel0 | Wroot0] split
__device__ __nv_bfloat16 g_B0lo[DIN*256];
__device__ __nv_bfloat16 g_B1hi[DHID*128];  // [Wrel1 | Wroot1] split
__device__ __nv_bfloat16 g_B1lo[DHID*128];
__device__ float g_y0 [NN*256];             // [x@Wrel0 | x@Wroot0]
__device__ float g_y1 [NN*128];             // [h@Wrel1 | h@Wroot1]
__device__ __nv_bfloat16 g_hh0[NN*DHID];    // split of h (layer-1 A input)
__device__ __nv_bfloat16 g_hl0[NN*DHID];
__device__ float g_h2 [NN*DOUT];            // final embeddings
__device__ __nv_bfloat16 g_hhi[NPAD*DOUT];  // split of normalized h (pad rows stay 0)
__device__ __nv_bfloat16 g_hlo[NPAD*DOUT];
__device__ int   g_pos  [2*EE];             // int32 edge indices (src | dst)
__device__ int   g_neg  [2*EE];
__device__ int   g_deg  [NN];               // CSR build
__device__ int   g_off  [NN+1];
__device__ int   g_rank [EE];               // per-edge rank within its dst bucket
__device__ int   g_srcs [EE];               // srcs grouped by dst
__device__ float g_loss [2];
__device__ int   g_done;                    // loss completion counter
__device__ int   g_is64;                    // edge index dtype flag

// ---------------- MUFU-free sigmoid for |x| <= ~1.01 ----------------
// sigmoid(x) = 0.5 + 0.5*tanh(x/2); odd Taylor of tanh to u^9, |u|<=0.5 -> err ~4e-6
__device__ __forceinline__ float sigmoid_poly(float x) {
    float u  = 0.5f * x;
    float u2 = u * u;
    float p = 2.1869488e-2f;
    p = fmaf(p, u2, -5.3968254e-2f);
    p = fmaf(p, u2,  1.3333334e-1f);
    p = fmaf(p, u2, -3.3333334e-1f);
    p = fmaf(p, u2,  1.0f);
    return fmaf(0.5f, u * p, 0.5f);
}

__device__ __forceinline__ void split_bf16(float v, __nv_bfloat16& hi, __nv_bfloat16& lo) {
    hi = __float2bfloat16(v);
    lo = __float2bfloat16(v - __bfloat162float(hi));
}

// ---------------- dtype detect ----------------
__global__ void detect_kernel(const void* p) {
    const unsigned* u = (const unsigned*)p;
    int lane = threadIdx.x & 31;
    int nz = 0;
    for (int i = lane; i < 64; i += 32) nz |= (u[2*i + 1] != 0u);
    for (int off = 16; off; off >>= 1) nz |= __shfl_xor_sync(0xffffffffu, nz, off);
    if (lane == 0) g_is64 = !nz;
}

// ---------------- zero deg + loss + done ----------------
__global__ void init_kernel() {
    int i = blockIdx.x * blockDim.x + threadIdx.x;
    if (i < NN) g_deg[i] = 0;
    if (i < 2)  g_loss[i] = 0.f;
    if (i == 2) g_done = 0;
}

// ---------------- edge convert + degree count (rank-capturing) ----------------
__global__ void convert_kernel(const void* p0, const void* p1) {
    int i = blockIdx.x * blockDim.x + threadIdx.x;
    if (i >= 2*EE) return;
    int vp, vn;
    if (g_is64) {
        vp = (int)((const long long*)p0)[i];
        vn = (int)((const long long*)p1)[i];
    } else {
        vp = ((const int*)p0)[i];
        vn = ((const int*)p1)[i];
    }
    g_pos[i] = vp;
    g_neg[i] = vn;
    if (i >= EE) g_rank[i - EE] = atomicAdd(&g_deg[vp], 1);   // dst entries: capture rank
}

// ---------------- exclusive scan of degrees (1 block) -- R5-proven version ----------------
__global__ __launch_bounds__(1024) void scan_kernel() {
    __shared__ int warp_sums[32];
    __shared__ int s_carry;
    int tid = threadIdx.x;
    if (tid == 0) s_carry = 0;
    __syncthreads();
    for (int base = 0; base < NN; base += 1024) {
        int i = base + tid;
        int v = (i < NN) ? g_deg[i] : 0;
        int x = v;
        #pragma unroll
        for (int off = 1; off < 32; off <<= 1) {
            int y = __shfl_up_sync(0xffffffffu, x, off);
            if ((tid & 31) >= off) x += y;
        }
        if ((tid & 31) == 31) warp_sums[tid >> 5] = x;
        __syncthreads();
        if (tid < 32) {
            int w = warp_sums[tid];
            int xs = w;
            #pragma unroll
            for (int off = 1; off < 32; off <<= 1) {
                int y = __shfl_up_sync(0xffffffffu, xs, off);
                if (tid >= off) xs += y;
            }
            warp_sums[tid] = xs - w;
        }
        __syncthreads();
        int incl = x + warp_sums[tid >> 5] + s_carry;
        int excl = incl - v;
        if (i < NN) g_off[i] = excl;
        __syncthreads();
        if (tid == 1023) s_carry = incl;
        __syncthreads();
    }
    if (tid == 0) g_off[NN] = s_carry;
}

// ---------------- fill CSR src lists (atomic-free: slot = off[d] + rank[e]) ----------------
__global__ void fill_kernel() {
    int e = blockIdx.x * blockDim.x + threadIdx.x;
    if (e >= EE) return;
    int d = g_pos[EE + e];
    g_srcs[g_off[d] + g_rank[e]] = g_pos[e];
}

// ---------------- x -> bf16 hi/lo split ----------------
__global__ void xsplit_kernel(const float* __restrict__ x) {
    int i = blockIdx.x * blockDim.x + threadIdx.x;
    if (i >= NN*DIN) return;
    __nv_bfloat16 hi, lo;
    split_bf16(x[i], hi, lo);
    g_xhi[i] = hi; g_xlo[i] = lo;
}

// ---------------- weights -> concat + split ----------------
__global__ void wsplit_kernel(const float* __restrict__ Wrel0, const float* __restrict__ Wroot0,
                              const float* __restrict__ Wrel1, const float* __restrict__ Wroot1) {
    int i = blockIdx.x * blockDim.x + threadIdx.x;
    if (i < DIN*256) {
        int k = i >> 8, n = i & 255;
        float w = (n < 128) ? Wrel0[k*128 + n] : Wroot0[k*128 + (n - 128)];
        __nv_bfloat16 hi, lo; split_bf16(w, hi, lo);
        g_B0hi[i] = hi; g_B0lo[i] = lo;
    } else if (i < DIN*256 + DHID*128) {
        int j = i - DIN*256;
        int k = j >> 7, n = j & 127;
        float w = (n < 64) ? Wrel1[k*64 + n] : Wroot1[k*64 + (n - 64)];
        __nv_bfloat16 hi, lo; split_bf16(w, hi, lo);
        g_B1hi[j] = hi; g_B1lo[j] = lo;
    }
}

// ---------------- WMMA split-precision GEMM: C[M,Nc] = A[M,128] @ B[128,Nc] ----------------
#define GLD 136
#define STG_LD 132
__global__ __launch_bounds__(512) void gemm_split_kernel(
    const __nv_bfloat16* __restrict__ Ahi_g, const __nv_bfloat16* __restrict__ Alo_g,
    const __nv_bfloat16* __restrict__ Bhi_g, const __nv_bfloat16* __restrict__ Blo_g,
    float* __restrict__ C, int M, int Nc)
{
    extern __shared__ char smraw[];
    __nv_bfloat16* Ahi = (__nv_bfloat16*)smraw;
    __nv_bfloat16* Alo = Ahi + 128 * GLD;
    __nv_bfloat16* Bhi = Alo + 128 * GLD;
    __nv_bfloat16* Blo = Bhi + 128 * GLD;

    int tid = threadIdx.x;
    int bi = blockIdx.y * 128, bc = blockIdx.x * 128;
    const int4 zero4 = make_int4(0, 0, 0, 0);

    for (int i = tid; i < 128 * 16; i += 512) {
        int r = i >> 4, c = (i & 15) * 8;
        int ar = bi + r;
        *(int4*)&Ahi[r * GLD + c] = (ar < M) ? *(const int4*)&Ahi_g[(size_t)ar * 128 + c] : zero4;
        *(int4*)&Alo[r * GLD + c] = (ar < M) ? *(const int4*)&Alo_g[(size_t)ar * 128 + c] : zero4;
        *(int4*)&Bhi[r * GLD + c] = *(const int4*)&Bhi_g[(size_t)r * Nc + bc + c];
        *(int4*)&Blo[r * GLD + c] = *(const int4*)&Blo_g[(size_t)r * Nc + bc + c];
    }
    __syncthreads();

    int warp = tid >> 5;
    int wm = (warp >> 2) * 32, wn = (warp & 3) * 32;

    wmma::fragment<wmma::accumulator, 16, 16, 16, float> acc[2][2];
    #pragma unroll
    for (int i = 0; i < 2; i++)
        #pragma unroll
        for (int j = 0; j < 2; j++) wmma::fill_fragment(acc[i][j], 0.f);

    #pragma unroll
    for (int k0 = 0; k0 < 8; k0++) {
        wmma::fragment<wmma::matrix_a, 16, 16, 16, __nv_bfloat16, wmma::row_major> ahi[2], alo[2];
        wmma::fragment<wmma::matrix_b, 16, 16, 16, __nv_bfloat16, wmma::row_major> bhi[2], blo[2];
        #pragma unroll
        for (int i = 0; i < 2; i++) {
            wmma::load_matrix_sync(ahi[i], &Ahi[(wm + i*16) * GLD + k0*16], GLD);
            wmma::load_matrix_sync(alo[i], &Alo[(wm + i*16) * GLD + k0*16], GLD);
        }
        #pragma unroll
        for (int j = 0; j < 2; j++) {
            wmma::load_matrix_sync(bhi[j], &Bhi[(k0*16) * GLD + wn + j*16], GLD);
            wmma::load_matrix_sync(blo[j], &Blo[(k0*16) * GLD + wn + j*16], GLD);
        }
        #pragma unroll
        for (int i = 0; i < 2; i++)
            #pragma unroll
            for (int j = 0; j < 2; j++) {
                wmma::mma_sync(acc[i][j], ahi[i], bhi[j], acc[i][j]);
                wmma::mma_sync(acc[i][j], ahi[i], blo[j], acc[i][j]);
                wmma::mma_sync(acc[i][j], alo[i], bhi[j], acc[i][j]);
            }
    }

    if (bi + 128 <= M) {
        #pragma unroll
        for (int i = 0; i < 2; i++)
            #pragma unroll
            for (int j = 0; j < 2; j++)
                wmma::store_matrix_sync(&C[(size_t)(bi + wm + i*16) * Nc + bc + wn + j*16],
                                        acc[i][j], Nc, wmma::mem_row_major);
    } else {
        __syncthreads();
        float* st = (float*)smraw;
        #pragma unroll
        for (int i = 0; i < 2; i++)
            #pragma unroll
            for (int j = 0; j < 2; j++)
                wmma::store_matrix_sync(&st[(wm + i*16) * STG_LD + wn + j*16],
                                        acc[i][j], STG_LD, wmma::mem_row_major);
        __syncthreads();
        for (int i = tid; i < 128 * 128; i += 512) {
            int r = i >> 7, c = i & 127;
            if (bi + r < M)
                C[(size_t)(bi + r) * Nc + bc + c] = st[r * STG_LD + c];
        }
    }
}

// ---------------- gather0: agg + root + bias -> tanh -> bf16 split (h) ----------------
__global__ void gather0_kernel(const float* __restrict__ b0) {
    int n = (blockIdx.x * blockDim.x + threadIdx.x) >> 5;
    int l = threadIdx.x & 31;
    if (n >= NN) return;
    int beg = g_off[n], end = g_off[n+1];
    float4 acc = make_float4(0.f, 0.f, 0.f, 0.f);
    int e = beg;
    for (; e + 3 < end; e += 4) {
        int s0 = g_srcs[e], s1 = g_srcs[e+1], s2 = g_srcs[e+2], s3 = g_srcs[e+3];
        float4 v0 = *(const float4*)&g_y0[(size_t)s0 * 256 + l*4];
        float4 v1 = *(const float4*)&g_y0[(size_t)s1 * 256 + l*4];
        float4 v2 = *(const float4*)&g_y0[(size_t)s2 * 256 + l*4];
        float4 v3 = *(const float4*)&g_y0[(size_t)s3 * 256 + l*4];
        acc.x += v0.x + v1.x + v2.x + v3.x;
        acc.y += v0.y + v1.y + v2.y + v3.y;
        acc.z += v0.z + v1.z + v2.z + v3.z;
        acc.w += v0.w + v1.w + v2.w + v3.w;
    }
    for (; e < end; e++) {
        int s = g_srcs[e];
        float4 v = *(const float4*)&g_y0[(size_t)s * 256 + l*4];
        acc.x += v.x; acc.y += v.y; acc.z += v.z; acc.w += v.w;
    }
    float4 r  = *(const float4*)&g_y0[(size_t)n * 256 + 128 + l*4];
    float4 bb = *(const float4*)&b0[l*4];
    float h0 = tanhf(acc.x + r.x + bb.x);
    float h1 = tanhf(acc.y + r.y + bb.y);
    float h2 = tanhf(acc.z + r.z + bb.z);
    float h3 = tanhf(acc.w + r.w + bb.w);
    __nv_bfloat16 a0, a1, a2, a3, c0, c1, c2, c3;
    split_bf16(h0, a0, c0); split_bf16(h1, a1, c1);
    split_bf16(h2, a2, c2); split_bf16(h3, a3, c3);
    int base = n * DHID + l*4;
    *(__nv_bfloat162*)&g_hh0[base]     = __halves2bfloat162(a0, a1);
    *(__nv_bfloat162*)&g_hh0[base + 2] = __halves2bfloat162(a2, a3);
    *(__nv_bfloat162*)&g_hl0[base]     = __halves2bfloat162(c0, c1);
    *(__nv_bfloat162*)&g_hl0[base + 2] = __halves2bfloat162(c2, c3);
}

// ---------------- gather1: agg + root + bias -> h2, normalize -> bf16 split ----------------
__global__ void gather1_kernel(const float* __restrict__ b1) {
    int n = (blockIdx.x * blockDim.x + threadIdx.x) >> 5;
    int l = threadIdx.x & 31;
    if (n >= NN) return;
    int beg = g_off[n], end = g_off[n+1];
    float2 acc = make_float2(0.f, 0.f);
    int e = beg;
    for (; e + 3 < end; e += 4) {
        int s0 = g_srcs[e], s1 = g_srcs[e+1], s2 = g_srcs[e+2], s3 = g_srcs[e+3];
        float2 v0 = *(const float2*)&g_y1[(size_t)s0 * 128 + l*2];
        float2 v1 = *(const float2*)&g_y1[(size_t)s1 * 128 + l*2];
        float2 v2 = *(const float2*)&g_y1[(size_t)s2 * 128 + l*2];
        float2 v3 = *(const float2*)&g_y1[(size_t)s3 * 128 + l*2];
        acc.x += v0.x + v1.x + v2.x + v3.x;
        acc.y += v0.y + v1.y + v2.y + v3.y;
    }
    for (; e < end; e++) {
        int s = g_srcs[e];
        float2 v = *(const float2*)&g_y1[(size_t)s * 128 + l*2];
        acc.x += v.x; acc.y += v.y;
    }
    float2 r = *(const float2*)&g_y1[(size_t)n * 128 + 64 + l*2];
    float x0 = acc.x + r.x + b1[l*2];
    float x1 = acc.y + r.y + b1[l*2 + 1];
    float ss = x0*x0 + x1*x1;
    for (int off = 16; off; off >>= 1) ss += __shfl_xor_sync(0xffffffffu, ss, off);
    float inv = 1.f / fmaxf(sqrtf(ss), 1e-8f);
    int base = n * DOUT + l*2;
    *(float2*)&g_h2[base] = make_float2(x0, x1);
    float n0 = x0 * inv, n1 = x1 * inv;
    __nv_bfloat16 h0, h1, l0, l1;
    split_bf16(n0, h0, l0); split_bf16(n1, h1, l1);
    *(__nv_bfloat162*)&g_hhi[base] = __halves2bfloat162(h0, h1);
    *(__nv_bfloat162*)&g_hlo[base] = __halves2bfloat162(l0, l1);
}

// ---------------- BCE reconstruction loss (self-finalizing) ----------------
__global__ __launch_bounds__(512) void loss_kernel(float* __restrict__ out, int write_out) {
    __shared__ float s_acc[2];
    if (threadIdx.x < 2) s_acc[threadIdx.x] = 0.f;
    __syncthreads();
    int gw = (blockIdx.x * blockDim.x + threadIdx.x) >> 5;
    int lane = threadIdx.x & 31;
    if (gw < 2*EE) {
        int isneg = (gw >= EE) ? 1 : 0;
        const int* ei = isneg ? g_neg : g_pos;
        int e = isneg ? gw - EE : gw;
        int s = ei[e], d = ei[EE + e];
        float2 a = *(const float2*)&g_h2[s * DOUT + lane * 2];
        float2 b = *(const float2*)&g_h2[d * DOUT + lane * 2];
        float dot = a.x*b.x + a.y*b.y;
        for (int off = 16; off; off >>= 1) dot += __shfl_xor_sync(0xffffffffu, dot, off);
        if (lane == 0) {
            float xx = isneg ? dot : -dot;
            float sp = (xx > 0.f) ? xx + log1pf(expf(-xx)) : log1pf(expf(xx));
            atomicAdd(&s_acc[isneg], sp);
        }
    }
    __syncthreads();
    if (threadIdx.x < 2) atomicAdd(&g_loss[threadIdx.x], s_acc[threadIdx.x]);
    __syncthreads();
    if (threadIdx.x == 0 && write_out) {
        __threadfence();
        int t = atomicAdd(&g_done, 1);
        if (t == gridDim.x - 1) {
            __threadfence();
            volatile float* gl = g_loss;
            out[(size_t)NN * NN] = gl[0] * (1.f / EE) + gl[1] * (1.f / EE);
        }
    }
}

// ---------------- sim = sigmoid(hn @ hn^T), symmetric: triangular 1D grid ----------------
// Block b -> (ti, tj), ti<=tj, via bounded integer decode. Off-diagonal tiles
// mirrored with a col-major accumulator store (free C^T).
#define LDA 72
__global__ __launch_bounds__(512) void sim_kernel(float* __restrict__ out) {
    // exact integer decode: row ti has (NT - ti) tiles
    int b = blockIdx.x;
    int ti = 0;
    #pragma unroll 1
    while (b >= NT - ti) { b -= NT - ti; ti++; }   // <= 79 iterations, strictly decreasing b
    int tj = ti + b;

    extern __shared__ char smraw[];
    __nv_bfloat16* Ahi = (__nv_bfloat16*)smraw;
    __nv_bfloat16* Alo = Ahi + 128 * LDA;
    __nv_bfloat16* Bhi = Alo + 128 * LDA;
    __nv_bfloat16* Blo = Bhi + 128 * LDA;

    int tid = threadIdx.x;
    int bi = ti * 128, bj = tj * 128;

    for (int i = tid; i < 128 * 8; i += 512) {
        int r = i >> 3, c = (i & 7) * 8;
        *(int4*)&Ahi[r * LDA + c] = *(const int4*)&g_hhi[(size_t)(bi + r) * DOUT + c];
        *(int4*)&Alo[r * LDA + c] = *(const int4*)&g_hlo[(size_t)(bi + r) * DOUT + c];
        *(int4*)&Bhi[r * LDA + c] = *(const int4*)&g_hhi[(size_t)(bj + r) * DOUT + c];
        *(int4*)&Blo[r * LDA + c] = *(const int4*)&g_hlo[(size_t)(bj + r) * DOUT + c];
    }
    __syncthreads();

    int warp = tid >> 5;
    int wm = (warp >> 2) * 32, wn = (warp & 3) * 32;

    wmma::fragment<wmma::accumulator, 16, 16, 16, float> acc[2][2];
    #pragma unroll
    for (int i = 0; i < 2; i++)
        #pragma unroll
        for (int j = 0; j < 2; j++) wmma::fill_fragment(acc[i][j], 0.f);

    #pragma unroll
    for (int k0 = 0; k0 < 4; k0++) {
        wmma::fragment<wmma::matrix_a, 16, 16, 16, __nv_bfloat16, wmma::row_major> ahi[2], alo[2];
        wmma::fragment<wmma::matrix_b, 16, 16, 16, __nv_bfloat16, wmma::col_major> bhi[2], blo[2];
        #pragma unroll
        for (int i = 0; i < 2; i++) {
            wmma::load_matrix_sync(ahi[i], &Ahi[(wm + i*16) * LDA + k0*16], LDA);
            wmma::load_matrix_sync(alo[i], &Alo[(wm + i*16) * LDA + k0*16], LDA);
        }
        #pragma unroll
        for (int j = 0; j < 2; j++) {
            wmma::load_matrix_sync(bhi[j], &Bhi[(wn + j*16) * LDA + k0*16], LDA);
            wmma::load_matrix_sync(blo[j], &Blo[(wn + j*16) * LDA + k0*16], LDA);
        }
        #pragma unroll
        for (int i = 0; i < 2; i++)
            #pragma unroll
            for (int j = 0; j < 2; j++) {
                wmma::mma_sync(acc[i][j], ahi[i], bhi[j], acc[i][j]);
                wmma::mma_sync(acc[i][j], ahi[i], blo[j], acc[i][j]);
                wmma::mma_sync(acc[i][j], alo[i], bhi[j], acc[i][j]);
            }
    }

    #pragma unroll
    for (int i = 0; i < 2; i++)
        #pragma unroll
        for (int j = 0; j < 2; j++)
            #pragma unroll
            for (int e = 0; e < acc[i][j].num_elements; e++)
                acc[i][j].x[e] = sigmoid_poly(acc[i][j].x[e]);

    bool interior = (bj + 128 <= NN);   // only tj==NT-1 is edge; ti<=tj so bi-edge implies bj-edge
    float* st = (float*)smraw;          // 128 x STG_LD floats (reuses tile smem)

    // ---- direct tile [bi, bj] ----
    if (interior) {
        #pragma unroll
        for (int i = 0; i < 2; i++)
            #pragma unroll
            for (int j = 0; j < 2; j++)
                wmma::store_matrix_sync(&out[(size_t)(bi + wm + i*16) * NN + bj + wn + j*16],
                                        acc[i][j], NN, wmma::mem_row_major);
    } else {
        __syncthreads();
        #pragma unroll
        for (int i = 0; i < 2; i++)
            #pragma unroll
            for (int j = 0; j < 2; j++)
                wmma::store_matrix_sync(&st[(wm + i*16) * STG_LD + wn + j*16],
                                        acc[i][j], STG_LD, wmma::mem_row_major);
        __syncthreads();
        for (int i = tid; i < 128 * 128; i += 512) {
            int r = i >> 7, c = i & 127;
            if (bi + r < NN && bj + c < NN)
                out[(size_t)(bi + r) * NN + bj + c] = st[r * STG_LD + c];
        }
    }

    // ---- mirrored tile [bj, bi] = C^T ----
    if (ti != tj) {
        if (interior) {
            // col-major store of C == row-major store of C^T at the mirrored origin
            #pragma unroll
            for (int i = 0; i < 2; i++)
                #pragma unroll
                for (int j = 0; j < 2; j++)
                    wmma::store_matrix_sync(&out[(size_t)(bj + wn + j*16) * NN + bi + wm + i*16],
                                            acc[i][j], NN, wmma::mem_col_major);
        } else {
            // edge path (tj == NT-1): st holds C from the staged branch above
            for (int i = tid; i < 128 * 128; i += 512) {
                int r = i >> 7, c = i & 127;            // mirrored row bj+r, col bi+c
                if (bj + r < NN && bi + c < NN)
                    out[(size_t)(bj + r) * NN + bi + c] = st[c * STG_LD + r];
            }
        }
    }
}

// ---------------- launcher ----------------
extern "C" void kernel_launch(void* const* d_in, const int* in_sizes, int n_in,
                              void* d_out, int out_size)
{
    const float* x      = (const float*)d_in[1];
    const void*  ei_raw = d_in[2];
    const void*  ne_raw = d_in[3];
    const float* Wrel0  = (const float*)d_in[4];
    const float* Wroot0 = (const float*)d_in[5];
    const float* b0     = (const float*)d_in[6];
    const float* Wrel1  = (const float*)d_in[7];
    const float* Wroot1 = (const float*)d_in[8];
    const float* b1     = (const float*)d_in[9];
    float* out = (float*)d_out;

    __nv_bfloat16 *xhi, *xlo, *B0hi, *B0lo, *B1hi, *B1lo, *hh0, *hl0;
    float *y0, *y1;
    cudaGetSymbolAddress((void**)&xhi,  g_xhi);
    cudaGetSymbolAddress((void**)&xlo,  g_xlo);
    cudaGetSymbolAddress((void**)&B0hi, g_B0hi);
    cudaGetSymbolAddress((void**)&B0lo, g_B0lo);
    cudaGetSymbolAddress((void**)&B1hi, g_B1hi);
    cudaGetSymbolAddress((void**)&B1lo, g_B1lo);
    cudaGetSymbolAddress((void**)&hh0,  g_hh0);
    cudaGetSymbolAddress((void**)&hl0,  g_hl0);
    cudaGetSymbolAddress((void**)&y0,   g_y0);
    cudaGetSymbolAddress((void**)&y1,   g_y1);

    const int smem_sim  = 4 * 128 * LDA * (int)sizeof(__nv_bfloat16);  // 73728
    const int smem_gemm = 4 * 128 * GLD * (int)sizeof(__nv_bfloat16);  // 139264
    cudaFuncSetAttribute(sim_kernel,  cudaFuncAttributeMaxDynamicSharedMemorySize, smem_sim);
    cudaFuncSetAttribute(gemm_split_kernel, cudaFuncAttributeMaxDynamicSharedMemorySize, smem_gemm);

    // edge normalize + CSR build (rank-capturing convert, atomic-free fill)
    detect_kernel<<<1, 32>>>(ei_raw);
    init_kernel<<<(NN + 255) / 256, 256>>>();
    convert_kernel<<<(2*EE + 255) / 256, 256>>>(ei_raw, ne_raw);
    scan_kernel<<<1, 1024>>>();
    fill_kernel<<<(EE + 255) / 256, 256>>>();

    // input / weight splits
    xsplit_kernel<<<(NN*DIN + 255) / 256, 256>>>(x);
    wsplit_kernel<<<(DIN*256 + DHID*128 + 255) / 256, 256>>>(Wrel0, Wroot0, Wrel1, Wroot1);

    // layer 0: y0 = x @ [Wrel0|Wroot0]; gather+tanh -> h (bf16 split)
    gemm_split_kernel<<<dim3(2, (NN + 127)/128), 512, smem_gemm>>>(xhi, xlo, B0hi, B0lo, y0, NN, 256);
    gather0_kernel<<<(NN*32 + 255) / 256, 256>>>(b0);

    // layer 1: y1 = h @ [Wrel1|Wroot1]; gather+finalize -> h2, hn split
    gemm_split_kernel<<<dim3(1, (NN + 127)/128), 512, smem_gemm>>>(hh0, hl0, B1hi, B1lo, y1, NN, 128);
    gather1_kernel<<<(NN*32 + 255) / 256, 256>>>(b1);

    // loss (self-finalizing: last block writes the scalar)
    int write_out = ((long long)out_size > (long long)NN * NN) ? 1 : 0;
    loss_kernel<<<(2*EE + 15) / 16, 512>>>(out, write_out);

    // dense sigmoid(hn @ hn^T), symmetric triangular grid
    sim_kernel<<<NTRI, 512, smem_sim>>>(out);
}

// round 12
// speedup vs baseline: 1.2959x; 1.2959x over previous
#include <cuda_runtime.h>
#include <cuda_bf16.h>
#include <mma.h>
#include <math.h>

using namespace nvcuda;

#define NN   10000
#define NPAD 10112          // 79 * 128
#define EE   320000
#define DIN  128
#define DHID 128
#define DOUT 64
#define NT   79             // number of 128-tiles
#define NTRI (NT*(NT+1)/2)  // 3160 upper-triangular tiles

// ---------------- scratch (static __device__ globals: allocation-free) ----------------
__device__ __nv_bfloat16 g_xhi[NN*DIN];     // bf16 hi/lo split of x
__device__ __nv_bfloat16 g_xlo[NN*DIN];
__device__ __nv_bfloat16 g_B0hi[DIN*256];   // [Wrel0 | Wroot0] split
__device__ __nv_bfloat16 g_B0lo[DIN*256];
__device__ __nv_bfloat16 g_B1hi[DHID*128];  // [Wrel1 | Wroot1] split
__device__ __nv_bfloat16 g_B1lo[DHID*128];
__device__ float g_y0 [NN*256];             // [x@Wrel0 | x@Wroot0]
__device__ float g_y1 [NN*128];             // [h@Wrel1 | h@Wroot1]
__device__ __nv_bfloat16 g_hh0[NN*DHID];    // split of h (layer-1 A input)
__device__ __nv_bfloat16 g_hl0[NN*DHID];
__device__ float g_h2 [NN*DOUT];            // final embeddings
__device__ __nv_bfloat16 g_hhi[NPAD*DOUT];  // split of normalized h (pad rows stay 0)
__device__ __nv_bfloat16 g_hlo[NPAD*DOUT];
__device__ int   g_pos  [2*EE];             // int32 edge indices (src | dst)
__device__ int   g_neg  [2*EE];
__device__ int   g_deg  [NN];               // CSR build
__device__ int   g_off  [NN+1];
__device__ int   g_cursor[NN];
__device__ int   g_srcs [EE];               // srcs grouped by dst
__device__ float g_loss [2];
__device__ int   g_is64;                    // edge index dtype flag

// ---------------- MUFU-free sigmoid for |x| <= ~1.01 ----------------
// sigmoid(x) = 0.5 + 0.5*tanh(x/2); odd Taylor of tanh to u^9, |u|<=0.5 -> err ~4e-6
__device__ __forceinline__ float sigmoid_poly(float x) {
    float u  = 0.5f * x;
    float u2 = u * u;
    float p = 2.1869488e-2f;
    p = fmaf(p, u2, -5.3968254e-2f);
    p = fmaf(p, u2,  1.3333334e-1f);
    p = fmaf(p, u2, -3.3333334e-1f);
    p = fmaf(p, u2,  1.0f);
    return fmaf(0.5f, u * p, 0.5f);
}

__device__ __forceinline__ void split_bf16(float v, __nv_bfloat16& hi, __nv_bfloat16& lo) {
    hi = __float2bfloat16(v);
    lo = __float2bfloat16(v - __bfloat162float(hi));
}

// ---------------- dtype detect ----------------
__global__ void detect_kernel(const void* p) {
    const unsigned* u = (const unsigned*)p;
    int lane = threadIdx.x & 31;
    int nz = 0;
    for (int i = lane; i < 64; i += 32) nz |= (u[2*i + 1] != 0u);
    for (int off = 16; off; off >>= 1) nz |= __shfl_xor_sync(0xffffffffu, nz, off);
    if (lane == 0) g_is64 = !nz;
}

// ---------------- zero deg + loss ----------------
__global__ void init_kernel() {
    int i = blockIdx.x * blockDim.x + threadIdx.x;
    if (i < NN) g_deg[i] = 0;
    if (i < 2)  g_loss[i] = 0.f;
}

// ---------------- edge convert + degree count (RED, no return) ----------------
__global__ void convert_kernel(const void* p0, const void* p1) {
    int i = blockIdx.x * blockDim.x + threadIdx.x;
    if (i >= 2*EE) return;
    int vp, vn;
    if (g_is64) {
        vp = (int)((const long long*)p0)[i];
        vn = (int)((const long long*)p1)[i];
    } else {
        vp = ((const int*)p0)[i];
        vn = ((const int*)p1)[i];
    }
    g_pos[i] = vp;
    g_neg[i] = vn;
    if (i >= EE) atomicAdd(&g_deg[vp], 1);   // dst entries
}

// ---------------- exclusive scan of degrees (1 block) -- proven version ----------------
__global__ __launch_bounds__(1024) void scan_kernel() {
    __shared__ int warp_sums[32];
    __shared__ int s_carry;
    int tid = threadIdx.x;
    if (tid == 0) s_carry = 0;
    __syncthreads();
    for (int base = 0; base < NN; base += 1024) {
        int i = base + tid;
        int v = (i < NN) ? g_deg[i] : 0;
        int x = v;
        #pragma unroll
        for (int off = 1; off < 32; off <<= 1) {
            int y = __shfl_up_sync(0xffffffffu, x, off);
            if ((tid & 31) >= off) x += y;
        }
        if ((tid & 31) == 31) warp_sums[tid >> 5] = x;
        __syncthreads();
        if (tid < 32) {
            int w = warp_sums[tid];
            int xs = w;
            #pragma unroll
            for (int off = 1; off < 32; off <<= 1) {
                int y = __shfl_up_sync(0xffffffffu, xs, off);
                if (tid >= off) xs += y;
            }
            warp_sums[tid] = xs - w;
        }
        __syncthreads();
        int incl = x + warp_sums[tid >> 5] + s_carry;
        int excl = incl - v;
        if (i < NN) { g_off[i] = excl; g_cursor[i] = excl; }
        __syncthreads();
        if (tid == 1023) s_carry = incl;
        __syncthreads();
    }
    if (tid == 0) g_off[NN] = s_carry;
}

// ---------------- fill CSR src lists (cursor atomics, proven) ----------------
__global__ void fill_kernel() {
    int e = blockIdx.x * blockDim.x + threadIdx.x;
    if (e >= EE) return;
    int d = g_pos[EE + e];
    int p = atomicAdd(&g_cursor[d], 1);
    g_srcs[p] = g_pos[e];
}

// ---------------- merged x + weights -> bf16 hi/lo split ----------------
#define XSPLIT_N (NN*DIN)
__global__ void split_kernel(const float* __restrict__ x,
                             const float* __restrict__ Wrel0, const float* __restrict__ Wroot0,
                             const float* __restrict__ Wrel1, const float* __restrict__ Wroot1) {
    int i = blockIdx.x * blockDim.x + threadIdx.x;
    if (i < XSPLIT_N) {
        __nv_bfloat16 hi, lo;
        split_bf16(x[i], hi, lo);
        g_xhi[i] = hi; g_xlo[i] = lo;
    } else {
        int j = i - XSPLIT_N;
        if (j < DIN*256) {
            int k = j >> 8, n = j & 255;
            float w = (n < 128) ? Wrel0[k*128 + n] : Wroot0[k*128 + (n - 128)];
            __nv_bfloat16 hi, lo; split_bf16(w, hi, lo);
            g_B0hi[j] = hi; g_B0lo[j] = lo;
        } else if (j < DIN*256 + DHID*128) {
            int m = j - DIN*256;
            int k = m >> 7, n = m & 127;
            float w = (n < 64) ? Wrel1[k*64 + n] : Wroot1[k*64 + (n - 64)];
            __nv_bfloat16 hi, lo; split_bf16(w, hi, lo);
            g_B1hi[m] = hi; g_B1lo[m] = lo;
        }
    }
}

// ---------------- WMMA split-precision GEMM: C[M,Nc] = A[M,128] @ B[128,Nc] ----------------
#define GLD 136
#define STG_LD 132
__global__ __launch_bounds__(512) void gemm_split_kernel(
    const __nv_bfloat16* __restrict__ Ahi_g, const __nv_bfloat16* __restrict__ Alo_g,
    const __nv_bfloat16* __restrict__ Bhi_g, const __nv_bfloat16* __restrict__ Blo_g,
    float* __restrict__ C, int M, int Nc)
{
    extern __shared__ char smraw[];
    __nv_bfloat16* Ahi = (__nv_bfloat16*)smraw;
    __nv_bfloat16* Alo = Ahi + 128 * GLD;
    __nv_bfloat16* Bhi = Alo + 128 * GLD;
    __nv_bfloat16* Blo = Bhi + 128 * GLD;

    int tid = threadIdx.x;
    int bi = blockIdx.y * 128, bc = blockIdx.x * 128;
    const int4 zero4 = make_int4(0, 0, 0, 0);

    for (int i = tid; i < 128 * 16; i += 512) {
        int r = i >> 4, c = (i & 15) * 8;
        int ar = bi + r;
        *(int4*)&Ahi[r * GLD + c] = (ar < M) ? *(const int4*)&Ahi_g[(size_t)ar * 128 + c] : zero4;
        *(int4*)&Alo[r * GLD + c] = (ar < M) ? *(const int4*)&Alo_g[(size_t)ar * 128 + c] : zero4;
        *(int4*)&Bhi[r * GLD + c] = *(const int4*)&Bhi_g[(size_t)r * Nc + bc + c];
        *(int4*)&Blo[r * GLD + c] = *(const int4*)&Blo_g[(size_t)r * Nc + bc + c];
    }
    __syncthreads();

    int warp = tid >> 5;
    int wm = (warp >> 2) * 32, wn = (warp & 3) * 32;

    wmma::fragment<wmma::accumulator, 16, 16, 16, float> acc[2][2];
    #pragma unroll
    for (int i = 0; i < 2; i++)
        #pragma unroll
        for (int j = 0; j < 2; j++) wmma::fill_fragment(acc[i][j], 0.f);

    #pragma unroll
    for (int k0 = 0; k0 < 8; k0++) {
        wmma::fragment<wmma::matrix_a, 16, 16, 16, __nv_bfloat16, wmma::row_major> ahi[2], alo[2];
        wmma::fragment<wmma::matrix_b, 16, 16, 16, __nv_bfloat16, wmma::row_major> bhi[2], blo[2];
        #pragma unroll
        for (int i = 0; i < 2; i++) {
            wmma::load_matrix_sync(ahi[i], &Ahi[(wm + i*16) * GLD + k0*16], GLD);
            wmma::load_matrix_sync(alo[i], &Alo[(wm + i*16) * GLD + k0*16], GLD);
        }
        #pragma unroll
        for (int j = 0; j < 2; j++) {
            wmma::load_matrix_sync(bhi[j], &Bhi[(k0*16) * GLD + wn + j*16], GLD);
            wmma::load_matrix_sync(blo[j], &Blo[(k0*16) * GLD + wn + j*16], GLD);
        }
        #pragma unroll
        for (int i = 0; i < 2; i++)
            #pragma unroll
            for (int j = 0; j < 2; j++) {
                wmma::mma_sync(acc[i][j], ahi[i], bhi[j], acc[i][j]);
                wmma::mma_sync(acc[i][j], ahi[i], blo[j], acc[i][j]);
                wmma::mma_sync(acc[i][j], alo[i], bhi[j], acc[i][j]);
            }
    }

    if (bi + 128 <= M) {
        #pragma unroll
        for (int i = 0; i < 2; i++)
            #pragma unroll
            for (int j = 0; j < 2; j++)
                wmma::store_matrix_sync(&C[(size_t)(bi + wm + i*16) * Nc + bc + wn + j*16],
                                        acc[i][j], Nc, wmma::mem_row_major);
    } else {
        __syncthreads();
        float* st = (float*)smraw;
        #pragma unroll
        for (int i = 0; i < 2; i++)
            #pragma unroll
            for (int j = 0; j < 2; j++)
                wmma::store_matrix_sync(&st[(wm + i*16) * STG_LD + wn + j*16],
                                        acc[i][j], STG_LD, wmma::mem_row_major);
        __syncthreads();
        for (int i = tid; i < 128 * 128; i += 512) {
            int r = i >> 7, c = i & 127;
            if (bi + r < M)
                C[(size_t)(bi + r) * Nc + bc + c] = st[r * STG_LD + c];
        }
    }
}

// ---------------- gather0: agg + root + bias -> tanh -> bf16 split (h) ----------------
__global__ void gather0_kernel(const float* __restrict__ b0) {
    int n = (blockIdx.x * blockDim.x + threadIdx.x) >> 5;
    int l = threadIdx.x & 31;
    if (n >= NN) return;
    int beg = g_off[n], end = g_off[n+1];
    float4 acc = make_float4(0.f, 0.f, 0.f, 0.f);
    int e = beg;
    for (; e + 3 < end; e += 4) {
        int s0 = g_srcs[e], s1 = g_srcs[e+1], s2 = g_srcs[e+2], s3 = g_srcs[e+3];
        float4 v0 = *(const float4*)&g_y0[(size_t)s0 * 256 + l*4];
        float4 v1 = *(const float4*)&g_y0[(size_t)s1 * 256 + l*4];
        float4 v2 = *(const float4*)&g_y0[(size_t)s2 * 256 + l*4];
        float4 v3 = *(const float4*)&g_y0[(size_t)s3 * 256 + l*4];
        acc.x += v0.x + v1.x + v2.x + v3.x;
        acc.y += v0.y + v1.y + v2.y + v3.y;
        acc.z += v0.z + v1.z + v2.z + v3.z;
        acc.w += v0.w + v1.w + v2.w + v3.w;
    }
    for (; e < end; e++) {
        int s = g_srcs[e];
        float4 v = *(const float4*)&g_y0[(size_t)s * 256 + l*4];
        acc.x += v.x; acc.y += v.y; acc.z += v.z; acc.w += v.w;
    }
    float4 r  = *(const float4*)&g_y0[(size_t)n * 256 + 128 + l*4];
    float4 bb = *(const float4*)&b0[l*4];
    float h0 = tanhf(acc.x + r.x + bb.x);
    float h1 = tanhf(acc.y + r.y + bb.y);
    float h2 = tanhf(acc.z + r.z + bb.z);
    float h3 = tanhf(acc.w + r.w + bb.w);
    __nv_bfloat16 a0, a1, a2, a3, c0, c1, c2, c3;
    split_bf16(h0, a0, c0); split_bf16(h1, a1, c1);
    split_bf16(h2, a2, c2); split_bf16(h3, a3, c3);
    int base = n * DHID + l*4;
    *(__nv_bfloat162*)&g_hh0[base]     = __halves2bfloat162(a0, a1);
    *(__nv_bfloat162*)&g_hh0[base + 2] = __halves2bfloat162(a2, a3);
    *(__nv_bfloat162*)&g_hl0[base]     = __halves2bfloat162(c0, c1);
    *(__nv_bfloat162*)&g_hl0[base + 2] = __halves2bfloat162(c2, c3);
}

// ---------------- gather1: agg + root + bias -> h2, normalize -> bf16 split ----------------
__global__ void gather1_kernel(const float* __restrict__ b1) {
    int n = (blockIdx.x * blockDim.x + threadIdx.x) >> 5;
    int l = threadIdx.x & 31;
    if (n >= NN) return;
    int beg = g_off[n], end = g_off[n+1];
    float2 acc = make_float2(0.f, 0.f);
    int e = beg;
    for (; e + 3 < end; e += 4) {
        int s0 = g_srcs[e], s1 = g_srcs[e+1], s2 = g_srcs[e+2], s3 = g_srcs[e+3];
        float2 v0 = *(const float2*)&g_y1[(size_t)s0 * 128 + l*2];
        float2 v1 = *(const float2*)&g_y1[(size_t)s1 * 128 + l*2];
        float2 v2 = *(const float2*)&g_y1[(size_t)s2 * 128 + l*2];
        float2 v3 = *(const float2*)&g_y1[(size_t)s3 * 128 + l*2];
        acc.x += v0.x + v1.x + v2.x + v3.x;
        acc.y += v0.y + v1.y + v2.y + v3.y;
    }
    for (; e < end; e++) {
        int s = g_srcs[e];
        float2 v = *(const float2*)&g_y1[(size_t)s * 128 + l*2];
        acc.x += v.x; acc.y += v.y;
    }
    float2 r = *(const float2*)&g_y1[(size_t)n * 128 + 64 + l*2];
    float x0 = acc.x + r.x + b1[l*2];
    float x1 = acc.y + r.y + b1[l*2 + 1];
    float ss = x0*x0 + x1*x1;
    for (int off = 16; off; off >>= 1) ss += __shfl_xor_sync(0xffffffffu, ss, off);
    float inv = 1.f / fmaxf(sqrtf(ss), 1e-8f);
    int base = n * DOUT + l*2;
    *(float2*)&g_h2[base] = make_float2(x0, x1);
    float n0 = x0 * inv, n1 = x1 * inv;
    __nv_bfloat16 h0, h1, l0, l1;
    split_bf16(n0, h0, l0); split_bf16(n1, h1, l1);
    *(__nv_bfloat162*)&g_hhi[base] = __halves2bfloat162(h0, h1);
    *(__nv_bfloat162*)&g_hlo[base] = __halves2bfloat162(l0, l1);
}

// ---------------- BCE reconstruction loss (8 lanes/edge, float4 loads) ----------------
__global__ __launch_bounds__(512) void loss_kernel() {
    __shared__ float s_acc[2];
    if (threadIdx.x < 2) s_acc[threadIdx.x] = 0.f;
    __syncthreads();
    int ge = (blockIdx.x * blockDim.x + threadIdx.x) >> 3;   // global edge id
    int sub = threadIdx.x & 7;
    if (ge < 2*EE) {
        int isneg = (ge >= EE) ? 1 : 0;
        const int* ei = isneg ? g_neg : g_pos;
        int e = isneg ? ge - EE : ge;
        int s = ei[e], d = ei[EE + e];
        const float4* pa = (const float4*)&g_h2[s * DOUT + sub * 8];
        const float4* pb = (const float4*)&g_h2[d * DOUT + sub * 8];
        float4 a0 = pa[0], a1 = pa[1];
        float4 b0 = pb[0], b1 = pb[1];
        float dot = a0.x*b0.x + a0.y*b0.y + a0.z*b0.z + a0.w*b0.w
                  + a1.x*b1.x + a1.y*b1.y + a1.z*b1.z + a1.w*b1.w;
        #pragma unroll
        for (int off = 4; off; off >>= 1) dot += __shfl_xor_sync(0xffffffffu, dot, off);
        if (sub == 0) {
            float xx = isneg ? dot : -dot;
            float sp = (xx > 0.f) ? xx + log1pf(expf(-xx)) : log1pf(expf(xx));
            atomicAdd(&s_acc[isneg], sp);
        }
    }
    __syncthreads();
    if (threadIdx.x < 2) atomicAdd(&g_loss[threadIdx.x], s_acc[threadIdx.x]);
}

__global__ void write_loss_kernel(float* out) {
    out[(size_t)NN * NN] = g_loss[0] * (1.f / EE) + g_loss[1] * (1.f / EE);
}

// ---------------- sim = sigmoid(hn @ hn^T), symmetric: triangular 1D grid ----------------
// Block b -> (ti, tj), ti<=tj, via bounded integer decode. Off-diagonal tiles
// mirrored with a col-major accumulator store (free C^T).
#define LDA 72
__global__ __launch_bounds__(512) void sim_kernel(float* __restrict__ out) {
    // exact integer decode: row ti has (NT - ti) tiles
    int b = blockIdx.x;
    int ti = 0;
    #pragma unroll 1
    while (b >= NT - ti) { b -= NT - ti; ti++; }   // <= 79 iterations, strictly decreasing b
    int tj = ti + b;

    extern __shared__ char smraw[];
    __nv_bfloat16* Ahi = (__nv_bfloat16*)smraw;
    __nv_bfloat16* Alo = Ahi + 128 * LDA;
    __nv_bfloat16* Bhi = Alo + 128 * LDA;
    __nv_bfloat16* Blo = Bhi + 128 * LDA;

    int tid = threadIdx.x;
    int bi = ti * 128, bj = tj * 128;

    for (int i = tid; i < 128 * 8; i += 512) {
        int r = i >> 3, c = (i & 7) * 8;
        *(int4*)&Ahi[r * LDA + c] = *(const int4*)&g_hhi[(size_t)(bi + r) * DOUT + c];
        *(int4*)&Alo[r * LDA + c] = *(const int4*)&g_hlo[(size_t)(bi + r) * DOUT + c];
        *(int4*)&Bhi[r * LDA + c] = *(const int4*)&g_hhi[(size_t)(bj + r) * DOUT + c];
        *(int4*)&Blo[r * LDA + c] = *(const int4*)&g_hlo[(size_t)(bj + r) * DOUT + c];
    }
    __syncthreads();

    int warp = tid >> 5;
    int wm = (warp >> 2) * 32, wn = (warp & 3) * 32;

    wmma::fragment<wmma::accumulator, 16, 16, 16, float> acc[2][2];
    #pragma unroll
    for (int i = 0; i < 2; i++)
        #pragma unroll
        for (int j = 0; j < 2; j++) wmma::fill_fragment(acc[i][j], 0.f);

    #pragma unroll
    for (int k0 = 0; k0 < 4; k0++) {
        wmma::fragment<wmma::matrix_a, 16, 16, 16, __nv_bfloat16, wmma::row_major> ahi[2], alo[2];
        wmma::fragment<wmma::matrix_b, 16, 16, 16, __nv_bfloat16, wmma::col_major> bhi[2], blo[2];
        #pragma unroll
        for (int i = 0; i < 2; i++) {
            wmma::load_matrix_sync(ahi[i], &Ahi[(wm + i*16) * LDA + k0*16], LDA);
            wmma::load_matrix_sync(alo[i], &Alo[(wm + i*16) * LDA + k0*16], LDA);
        }
        #pragma unroll
        for (int j = 0; j < 2; j++) {
            wmma::load_matrix_sync(bhi[j], &Bhi[(wn + j*16) * LDA + k0*16], LDA);
            wmma::load_matrix_sync(blo[j], &Blo[(wn + j*16) * LDA + k0*16], LDA);
        }
        #pragma unroll
        for (int i = 0; i < 2; i++)
            #pragma unroll
            for (int j = 0; j < 2; j++) {
                wmma::mma_sync(acc[i][j], ahi[i], bhi[j], acc[i][j]);
                wmma::mma_sync(acc[i][j], ahi[i], blo[j], acc[i][j]);
                wmma::mma_sync(acc[i][j], alo[i], bhi[j], acc[i][j]);
            }
    }

    #pragma unroll
    for (int i = 0; i < 2; i++)
        #pragma unroll
        for (int j = 0; j < 2; j++)
            #pragma unroll
            for (int e = 0; e < acc[i][j].num_elements; e++)
                acc[i][j].x[e] = sigmoid_poly(acc[i][j].x[e]);

    bool interior = (bj + 128 <= NN);   // only tj==NT-1 is edge; ti<=tj so bi-edge implies bj-edge
    float* st = (float*)smraw;          // 128 x STG_LD floats (reuses tile smem)

    // ---- direct tile [bi, bj] ----
    if (interior) {
        #pragma unroll
        for (int i = 0; i < 2; i++)
            #pragma unroll
            for (int j = 0; j < 2; j++)
                wmma::store_matrix_sync(&out[(size_t)(bi + wm + i*16) * NN + bj + wn + j*16],
                                        acc[i][j], NN, wmma::mem_row_major);
    } else {
        __syncthreads();
        #pragma unroll
        for (int i = 0; i < 2; i++)
            #pragma unroll
            for (int j = 0; j < 2; j++)
                wmma::store_matrix_sync(&st[(wm + i*16) * STG_LD + wn + j*16],
                                        acc[i][j], STG_LD, wmma::mem_row_major);
        __syncthreads();
        for (int i = tid; i < 128 * 128; i += 512) {
            int r = i >> 7, c = i & 127;
            if (bi + r < NN && bj + c < NN)
                out[(size_t)(bi + r) * NN + bj + c] = st[r * STG_LD + c];
        }
    }

    // ---- mirrored tile [bj, bi] = C^T ----
    if (ti != tj) {
        if (interior) {
            // col-major store of C == row-major store of C^T at the mirrored origin
            #pragma unroll
            for (int i = 0; i < 2; i++)
                #pragma unroll
                for (int j = 0; j < 2; j++)
                    wmma::store_matrix_sync(&out[(size_t)(bj + wn + j*16) * NN + bi + wm + i*16],
                                            acc[i][j], NN, wmma::mem_col_major);
        } else {
            // edge path (tj == NT-1): st holds C from the staged branch above
            for (int i = tid; i < 128 * 128; i += 512) {
                int r = i >> 7, c = i & 127;            // mirrored row bj+r, col bi+c
                if (bj + r < NN && bi + c < NN)
                    out[(size_t)(bj + r) * NN + bi + c] = st[c * STG_LD + r];
            }
        }
    }
}

// ---------------- launcher ----------------
extern "C" void kernel_launch(void* const* d_in, const int* in_sizes, int n_in,
                              void* d_out, int out_size)
{
    const float* x      = (const float*)d_in[1];
    const void*  ei_raw = d_in[2];
    const void*  ne_raw = d_in[3];
    const float* Wrel0  = (const float*)d_in[4];
    const float* Wroot0 = (const float*)d_in[5];
    const float* b0     = (const float*)d_in[6];
    const float* Wrel1  = (const float*)d_in[7];
    const float* Wroot1 = (const float*)d_in[8];
    const float* b1     = (const float*)d_in[9];
    float* out = (float*)d_out;

    __nv_bfloat16 *xhi, *xlo, *B0hi, *B0lo, *B1hi, *B1lo, *hh0, *hl0;
    float *y0, *y1;
    cudaGetSymbolAddress((void**)&xhi,  g_xhi);
    cudaGetSymbolAddress((void**)&xlo,  g_xlo);
    cudaGetSymbolAddress((void**)&B0hi, g_B0hi);
    cudaGetSymbolAddress((void**)&B0lo, g_B0lo);
    cudaGetSymbolAddress((void**)&B1hi, g_B1hi);
    cudaGetSymbolAddress((void**)&B1lo, g_B1lo);
    cudaGetSymbolAddress((void**)&hh0,  g_hh0);
    cudaGetSymbolAddress((void**)&hl0,  g_hl0);
    cudaGetSymbolAddress((void**)&y0,   g_y0);
    cudaGetSymbolAddress((void**)&y1,   g_y1);

    const int smem_sim  = 4 * 128 * LDA * (int)sizeof(__nv_bfloat16);  // 73728
    const int smem_gemm = 4 * 128 * GLD * (int)sizeof(__nv_bfloat16);  // 139264
    cudaFuncSetAttribute(sim_kernel,  cudaFuncAttributeMaxDynamicSharedMemorySize, smem_sim);
    cudaFuncSetAttribute(gemm_split_kernel, cudaFuncAttributeMaxDynamicSharedMemorySize, smem_gemm);

    // edge normalize + CSR build (R10-proven path)
    detect_kernel<<<1, 32>>>(ei_raw);
    init_kernel<<<(NN + 255) / 256, 256>>>();
    convert_kernel<<<(2*EE + 255) / 256, 256>>>(ei_raw, ne_raw);
    scan_kernel<<<1, 1024>>>();
    fill_kernel<<<(EE + 255) / 256, 256>>>();

    // merged input / weight splits
    split_kernel<<<(XSPLIT_N + DIN*256 + DHID*128 + 255) / 256, 256>>>(x, Wrel0, Wroot0, Wrel1, Wroot1);

    // layer 0: y0 = x @ [Wrel0|Wroot0]; gather+tanh -> h (bf16 split)
    gemm_split_kernel<<<dim3(2, (NN + 127)/128), 512, smem_gemm>>>(xhi, xlo, B0hi, B0lo, y0, NN, 256);
    gather0_kernel<<<(NN*32 + 255) / 256, 256>>>(b0);

    // layer 1: y1 = h @ [Wrel1|Wroot1]; gather+finalize -> h2, hn split
    gemm_split_kernel<<<dim3(1, (NN + 127)/128), 512, smem_gemm>>>(hh0, hl0, B1hi, B1lo, y1, NN, 128);
    gather1_kernel<<<(NN*32 + 255) / 256, 256>>>(b1);

    // loss (8 lanes/edge)
    loss_kernel<<<(2*EE*8 + 511) / 512, 512>>>();
    if ((long long)out_size > (long long)NN * NN)
        write_loss_kernel<<<1, 1>>>(out);

    // dense sigmoid(hn @ hn^T), symmetric triangular grid
    sim_kernel<<<NTRI, 512, smem_sim>>>(out);
}